// round 5
// baseline (speedup 1.0000x reference)
#include <cuda_runtime.h>
#include <cuda_bf16.h>
#include <cstdint>

using bf16 = __nv_bfloat16;

#define H 1024
#define BATCH 8
#define SEQ 2048
#define ROWS (BATCH * SEQ)   // 16384

// ---- GEMM tile config: 128x128x64, 4 warps (2x2), warp tile 64x64 ----
#define BM 128
#define BN 128
#define BK 64
#define NSTG 3
#define STG_BYTES (2 * BM * BK * 2)          // A(16KB)+B(16KB) = 32KB per stage
#define SMEM_BYTES (NSTG * STG_BYTES)        // 96KB -> 2 CTAs/SM

// ---------------- scratch (static device globals; no allocation) ----------------
__device__ float g_xqn_f32[(size_t)ROWS * H];          // 64 MB
__device__ bf16  g_xqn_bf [(size_t)ROWS * H];          // 32 MB
__device__ bf16  g_kr     [(size_t)ROWS * H];          // 32 MB
__device__ bf16  g_vr     [(size_t)ROWS * H];          // 32 MB
__device__ bf16  g_qr     [(size_t)ROWS * H];          // 32 MB (pre-scaled 1/32)
__device__ bf16  g_E      [(size_t)BATCH * SEQ * SEQ]; // 64 MB
__device__ bf16  g_qWb    [(size_t)H * H];             // 2 MB
__device__ float g_gate   [H];
__device__ float g_Zpart  [BATCH * 256];
__device__ float g_Zinv   [BATCH];

__device__ __forceinline__ float sigmoidf(float x) { return 1.f / (1.f + expf(-x)); }

__device__ __forceinline__ void store_bf4(bf16* p, float a, float b, float c, float d) {
    __nv_bfloat162 lo = __floats2bfloat162_rn(a, b);
    __nv_bfloat162 hi = __floats2bfloat162_rn(c, d);
    uint2 u;
    u.x = *reinterpret_cast<unsigned*>(&lo);
    u.y = *reinterpret_cast<unsigned*>(&hi);
    *reinterpret_cast<uint2*>(p) = u;
}

__device__ __forceinline__ uint32_t smem_u32(const void* p) {
    uint32_t a;
    asm("{ .reg .u64 t; cvta.to.shared.u64 t, %1; cvt.u32.u64 %0, t; }" : "=r"(a) : "l"(p));
    return a;
}

__device__ __forceinline__ void cp16(uint32_t dst, const void* src) {
    asm volatile("cp.async.cg.shared.global [%0], [%1], 16;" :: "r"(dst), "l"(src) : "memory");
}
#define CP_COMMIT() asm volatile("cp.async.commit_group;" ::: "memory")
#define CP_WAIT1()  asm volatile("cp.async.wait_group 1;" ::: "memory")

__device__ __forceinline__ void ldsm4(uint32_t* r, uint32_t a) {
    asm volatile("ldmatrix.sync.aligned.m8n8.x4.shared.b16 {%0,%1,%2,%3}, [%4];"
                 : "=r"(r[0]), "=r"(r[1]), "=r"(r[2]), "=r"(r[3]) : "r"(a));
}
__device__ __forceinline__ void ldsm4t(uint32_t* r, uint32_t a) {
    asm volatile("ldmatrix.sync.aligned.m8n8.x4.trans.shared.b16 {%0,%1,%2,%3}, [%4];"
                 : "=r"(r[0]), "=r"(r[1]), "=r"(r[2]), "=r"(r[3]) : "r"(a));
}

__device__ __forceinline__ void mma16816(float* c, const uint32_t* a, uint32_t b0, uint32_t b1) {
    asm volatile(
        "mma.sync.aligned.m16n8k16.row.col.f32.bf16.bf16.f32 "
        "{%0,%1,%2,%3}, {%4,%5,%6,%7}, {%8,%9}, {%0,%1,%2,%3};"
        : "+f"(c[0]), "+f"(c[1]), "+f"(c[2]), "+f"(c[3])
        : "r"(a[0]), "r"(a[1]), "r"(a[2]), "r"(a[3]), "r"(b0), "r"(b1));
}

// ---------------- small prep kernels ----------------
__global__ void cvt_qw_kernel(const float* __restrict__ qW) {
    int i = blockIdx.x * blockDim.x + threadIdx.x;
    if (i < H * H) g_qWb[i] = __float2bfloat16(qW[i]);
}

__global__ void gate_kernel(const float* __restrict__ v_prime,
                            const float* __restrict__ v1W, const float* __restrict__ v1b,
                            const float* __restrict__ v2W, const float* __restrict__ v2b) {
    int warp = (blockIdx.x * blockDim.x + threadIdx.x) >> 5;
    int lane = threadIdx.x & 31;
    if (warp >= H) return;
    float s1 = 0.f, s2 = 0.f;
    for (int i = lane; i < H; i += 32) {
        float vp = sigmoidf(v_prime[i]);
        s1 += vp * v1W[warp * H + i];
        s2 += vp * v2W[warp * H + i];
    }
#pragma unroll
    for (int o = 16; o; o >>= 1) {
        s1 += __shfl_xor_sync(0xffffffffu, s1, o);
        s2 += __shfl_xor_sync(0xffffffffu, s2, o);
    }
    if (lane == 0)
        g_gate[warp] = sigmoidf(s1 + v1b[warp]) * tanhf(s2 + v2b[warp]);
}

// ---------------- fused dual LayerNorm + elementwise ----------------
__global__ void ln_kernel(const float* __restrict__ x,
                          const float* __restrict__ qn_w, const float* __restrict__ qn_b,
                          const float* __restrict__ kvn_w, const float* __restrict__ kvn_b,
                          const float* __restrict__ k_prime) {
    int row = blockIdx.x;
    int tid = threadIdx.x;
    size_t base = (size_t)row * H;
    float4 v = *reinterpret_cast<const float4*>(x + base + tid * 4);
    float s  = v.x + v.y + v.z + v.w;
    float ss = v.x * v.x + v.y * v.y + v.z * v.z + v.w * v.w;
#pragma unroll
    for (int o = 16; o; o >>= 1) {
        s  += __shfl_xor_sync(0xffffffffu, s, o);
        ss += __shfl_xor_sync(0xffffffffu, ss, o);
    }
    __shared__ float shs[8], shss[8];
    int w = tid >> 5, l = tid & 31;
    if (l == 0) { shs[w] = s; shss[w] = ss; }
    __syncthreads();
    float ts = 0.f, tss = 0.f;
#pragma unroll
    for (int i = 0; i < 8; i++) { ts += shs[i]; tss += shss[i]; }
    float mean = ts * (1.f / H);
    float var  = tss * (1.f / H) - mean * mean;
    float rstd = rsqrtf(var + 1e-5f);

    int j = tid * 4;
    float4 qw  = *reinterpret_cast<const float4*>(qn_w + j);
    float4 qb4 = *reinterpret_cast<const float4*>(qn_b + j);
    float4 kw  = *reinterpret_cast<const float4*>(kvn_w + j);
    float4 kb4 = *reinterpret_cast<const float4*>(kvn_b + j);
    float4 kp  = *reinterpret_cast<const float4*>(k_prime + j);
    float4 gt  = *reinterpret_cast<const float4*>(g_gate + j);

    float xh0 = (v.x - mean) * rstd, xh1 = (v.y - mean) * rstd;
    float xh2 = (v.z - mean) * rstd, xh3 = (v.w - mean) * rstd;

    float xq0 = xh0 * qw.x + qb4.x, xq1 = xh1 * qw.y + qb4.y;
    float xq2 = xh2 * qw.z + qb4.z, xq3 = xh3 * qw.w + qb4.w;
    float xk0 = xh0 * kw.x + kb4.x, xk1 = xh1 * kw.y + kb4.y;
    float xk2 = xh2 * kw.z + kb4.z, xk3 = xh3 * kw.w + kb4.w;

    *reinterpret_cast<float4*>(g_xqn_f32 + base + j) = make_float4(xq0, xq1, xq2, xq3);
    store_bf4(g_xqn_bf + base + j, xq0, xq1, xq2, xq3);
    store_bf4(g_kr + base + j, xk0 * sigmoidf(kp.x), xk1 * sigmoidf(kp.y),
                               xk2 * sigmoidf(kp.z), xk3 * sigmoidf(kp.w));
    store_bf4(g_vr + base + j, xk0 * gt.x, xk1 * gt.y, xk2 * gt.z, xk3 * gt.w);
}

// ---------------- pipelined mma.sync GEMM (frag double-buffered) ----------------
// EK = 0: qr  = (xqn_bf @ qWb^T + qb) * sigmoid(q') / 32   [B:(N,K)]   -> g_qr
// EK = 1: E   = exp(qr @ kr^T)                              [B:(N,K)]   -> g_E + Z partials
// EK = 2: out = (E @ vr) * Zinv[b] + xqn_f32                [B:(K,N)]   -> d_out
template<int EK>
__global__ void __launch_bounds__(128, 2)
gemm_mma(const float* __restrict__ e0, const float* __restrict__ e1,
         float* __restrict__ outf) {
    constexpr bool TRB = (EK == 2);           // B stored [K,N] row-major -> ldmatrix.trans
    constexpr int Kdim = (EK == 2) ? 2048 : 1024;
    constexpr int LDA  = (EK == 2) ? 2048 : 1024;
    constexpr int LDB  = 1024;                // qWb/kr: [N,1024]; vr: [K,1024]
    constexpr int KT   = Kdim / BK;

    extern __shared__ char smem[];
    uint32_t sm = smem_u32(smem);

    int tid  = threadIdx.x;
    int lane = tid & 31, w = tid >> 5;
    int wm = w >> 1, wn = w & 1;              // 2x2 warp grid, 64x64 warp tiles
    int bz = blockIdx.z;
    int m0 = blockIdx.y * BM, n0 = blockIdx.x * BN;

    const bf16 *A, *B;
    if (EK == 0)      { A = g_xqn_bf;                       B = g_qWb; }
    else if (EK == 1) { A = g_qr + (size_t)bz * SEQ * H;    B = g_kr + (size_t)bz * SEQ * H; }
    else              { A = g_E  + (size_t)bz * SEQ * SEQ;  B = g_vr + (size_t)bz * SEQ * H; }

    // ---- A loader geometry (128 rows x 64 cols, pitch 128B, 8 chunks/row) ----
    int ar_ = tid >> 3, ac_ = tid & 7;
    uint32_t aswz = (uint32_t)((ac_ ^ (ar_ & 7)) << 4);
    const char* Ag = (const char*)(A + (size_t)(m0 + ar_) * LDA) + ac_ * 16;

    // ---- B loader geometry ----
    int br_, bc_;
    uint32_t bswz;
    const char* Bg;
    if (TRB) {
        br_ = tid >> 4; bc_ = tid & 15;
        bswz = (uint32_t)((((bc_ & 7) ^ (br_ & 7)) | (bc_ & 8)) << 4);
        Bg = (const char*)(B + (size_t)br_ * LDB + n0 + bc_ * 8);
    } else {
        br_ = ar_; bc_ = ac_;
        bswz = aswz;
        Bg = (const char*)(B + (size_t)(n0 + br_) * LDB) + bc_ * 16;
    }

    auto load_tile = [&](int s, int kt) {
        uint32_t base = sm + s * STG_BYTES;
        const char* ag = Ag + (size_t)kt * (BK * 2);
#pragma unroll
        for (int i = 0; i < 8; i++)
            cp16(base + (uint32_t)(ar_ + i * 16) * 128 + aswz, ag + (size_t)i * 16 * LDA * 2);
        uint32_t bb = base + 16384u;
        if (TRB) {
            const char* bg = Bg + (size_t)kt * BK * LDB * 2;
#pragma unroll
            for (int i = 0; i < 8; i++)
                cp16(bb + (uint32_t)(br_ + i * 8) * 256 + bswz, bg + (size_t)i * 8 * LDB * 2);
        } else {
            const char* bg = Bg + (size_t)kt * (BK * 2);
#pragma unroll
            for (int i = 0; i < 8; i++)
                cp16(bb + (uint32_t)(br_ + i * 16) * 128 + bswz, bg + (size_t)i * 16 * LDB * 2);
        }
    };

    load_tile(0, 0); CP_COMMIT();
    load_tile(1, 1); CP_COMMIT();

    float acc[4][8][4];
#pragma unroll
    for (int i = 0; i < 4; i++)
#pragma unroll
        for (int j = 0; j < 8; j++)
#pragma unroll
            for (int q = 0; q < 4; q++) acc[i][j][q] = 0.f;

    int rlA = wm * 64 + (lane & 15);
    int hi  = lane >> 4;
    int rlB = wn * 64 + (lane & 15);
    int tK  = lane & 15;
    int tN  = wn * 8 + (lane >> 4);

    // fragment double buffers
    uint32_t arf[2][4][4], brf[2][4][4];

    for (int kt = 0; kt < KT; kt++) {
        CP_WAIT1();
        __syncthreads();
        int s = kt % NSTG;
        uint32_t sA = sm + s * STG_BYTES;
        uint32_t sB = sA + 16384u;

        int nt = kt + NSTG - 1;
        if (nt < KT) load_tile(nt % NSTG, nt);
        CP_COMMIT();

        // prologue: frags for ks=0 into buffer 0
        {
            int chunk = hi;
#pragma unroll
            for (int mi = 0; mi < 4; mi++) {
                int r = rlA + mi * 16;
                ldsm4(arf[0][mi], sA + (uint32_t)r * 128 + (uint32_t)((chunk ^ (r & 7)) << 4));
            }
            if (TRB) {
                int r = tK;
#pragma unroll
                for (int nj = 0; nj < 4; nj++) {
                    int cn = tN + nj * 2;
                    uint32_t phys = (uint32_t)((((cn & 7) ^ (r & 7)) | (cn & 8)) << 4);
                    ldsm4t(brf[0][nj], sB + (uint32_t)r * 256 + phys);
                }
            } else {
#pragma unroll
                for (int nj = 0; nj < 4; nj++) {
                    int r = rlB + nj * 16;
                    ldsm4(brf[0][nj], sB + (uint32_t)r * 128 + (uint32_t)((chunk ^ (r & 7)) << 4));
                }
            }
        }

#pragma unroll
        for (int ks = 0; ks < 4; ks++) {
            const int cur = ks & 1, nxt = cur ^ 1;
            // prefetch frags for ks+1 (issue before MMAs so LDSM latency hides)
            if (ks < 3) {
                int chunk = (ks + 1) * 2 + hi;
#pragma unroll
                for (int mi = 0; mi < 4; mi++) {
                    int r = rlA + mi * 16;
                    ldsm4(arf[nxt][mi], sA + (uint32_t)r * 128 + (uint32_t)((chunk ^ (r & 7)) << 4));
                }
                if (TRB) {
                    int r = (ks + 1) * 16 + tK;
#pragma unroll
                    for (int nj = 0; nj < 4; nj++) {
                        int cn = tN + nj * 2;
                        uint32_t phys = (uint32_t)((((cn & 7) ^ (r & 7)) | (cn & 8)) << 4);
                        ldsm4t(brf[nxt][nj], sB + (uint32_t)r * 256 + phys);
                    }
                } else {
#pragma unroll
                    for (int nj = 0; nj < 4; nj++) {
                        int r = rlB + nj * 16;
                        ldsm4(brf[nxt][nj], sB + (uint32_t)r * 128 + (uint32_t)((chunk ^ (r & 7)) << 4));
                    }
                }
            }
            // MMAs on current buffer
            if (TRB) {
#pragma unroll
                for (int mi = 0; mi < 4; mi++)
#pragma unroll
                    for (int nj = 0; nj < 4; nj++) {
                        mma16816(acc[mi][nj * 2 + 0], arf[cur][mi], brf[cur][nj][0], brf[cur][nj][1]);
                        mma16816(acc[mi][nj * 2 + 1], arf[cur][mi], brf[cur][nj][2], brf[cur][nj][3]);
                    }
            } else {
#pragma unroll
                for (int mi = 0; mi < 4; mi++)
#pragma unroll
                    for (int nj = 0; nj < 4; nj++) {
                        mma16816(acc[mi][nj * 2 + 0], arf[cur][mi], brf[cur][nj][0], brf[cur][nj][2]);
                        mma16816(acc[mi][nj * 2 + 1], arf[cur][mi], brf[cur][nj][1], brf[cur][nj][3]);
                    }
            }
        }
    }

    // ---------------- register epilogue ----------------
    float zs = 0.f;
    float zi = (EK == 2) ? g_Zinv[bz] : 0.f;

#pragma unroll
    for (int nj = 0; nj < 8; nj++) {
        int col = n0 + wn * 64 + nj * 8 + (lane & 3) * 2;
        float b0 = 0.f, b1 = 0.f, p0 = 0.f, p1 = 0.f;
        if (EK == 0) {
            float2 bb = *reinterpret_cast<const float2*>(e0 + col);
            float2 pp = *reinterpret_cast<const float2*>(e1 + col);
            b0 = bb.x; b1 = bb.y;
            p0 = sigmoidf(pp.x) * 0.03125f;
            p1 = sigmoidf(pp.y) * 0.03125f;
        }
#pragma unroll
        for (int mi = 0; mi < 4; mi++) {
            int r0 = m0 + wm * 64 + mi * 16 + (lane >> 2);
            int r1 = r0 + 8;
            float* c = acc[mi][nj];
            if (EK == 0) {
                __nv_bfloat162 u0 = __floats2bfloat162_rn((c[0] + b0) * p0, (c[1] + b1) * p1);
                __nv_bfloat162 u1 = __floats2bfloat162_rn((c[2] + b0) * p0, (c[3] + b1) * p1);
                *reinterpret_cast<__nv_bfloat162*>(g_qr + (size_t)r0 * H + col) = u0;
                *reinterpret_cast<__nv_bfloat162*>(g_qr + (size_t)r1 * H + col) = u1;
            } else if (EK == 1) {
                __nv_bfloat162 u0 = __floats2bfloat162_rn(expf(c[0]), expf(c[1]));
                __nv_bfloat162 u1 = __floats2bfloat162_rn(expf(c[2]), expf(c[3]));
                zs += __bfloat162float(u0.x) + __bfloat162float(u0.y)
                    + __bfloat162float(u1.x) + __bfloat162float(u1.y);
                size_t bb = (size_t)bz * SEQ * SEQ;
                *reinterpret_cast<__nv_bfloat162*>(g_E + bb + (size_t)r0 * SEQ + col) = u0;
                *reinterpret_cast<__nv_bfloat162*>(g_E + bb + (size_t)r1 * SEQ + col) = u1;
            } else {
                size_t o0 = ((size_t)bz * SEQ + r0) * H + col;
                size_t o1 = ((size_t)bz * SEQ + r1) * H + col;
                float2 x0 = *reinterpret_cast<const float2*>(g_xqn_f32 + o0);
                float2 x1 = *reinterpret_cast<const float2*>(g_xqn_f32 + o1);
                *reinterpret_cast<float2*>(outf + o0) =
                    make_float2(c[0] * zi + x0.x, c[1] * zi + x0.y);
                *reinterpret_cast<float2*>(outf + o1) =
                    make_float2(c[2] * zi + x1.x, c[3] * zi + x1.y);
            }
        }
    }

    if (EK == 1) {
        __shared__ float red[4];
#pragma unroll
        for (int o = 16; o; o >>= 1) zs += __shfl_xor_sync(0xffffffffu, zs, o);
        if (lane == 0) red[w] = zs;
        __syncthreads();
        if (tid == 0)
            g_Zpart[bz * 256 + blockIdx.y * gridDim.x + blockIdx.x] =
                red[0] + red[1] + red[2] + red[3];
    }
}

// deterministic fixed-order reduction -> 1/Z per batch
__global__ void zreduce_kernel() {
    int b = blockIdx.x, tid = threadIdx.x;
    __shared__ float sh[256];
    sh[tid] = g_Zpart[b * 256 + tid];
    __syncthreads();
    for (int o = 128; o; o >>= 1) {
        if (tid < o) sh[tid] += sh[tid + o];
        __syncthreads();
    }
    if (tid == 0) g_Zinv[b] = 1.f / sh[0];
}

// ---------------- launch ----------------
extern "C" void kernel_launch(void* const* d_in, const int* in_sizes, int n_in,
                              void* d_out, int out_size) {
    const float* x       = (const float*)d_in[0];
    const float* qn_w    = (const float*)d_in[1];
    const float* qn_b    = (const float*)d_in[2];
    const float* kvn_w   = (const float*)d_in[3];
    const float* kvn_b   = (const float*)d_in[4];
    const float* q_prime = (const float*)d_in[5];
    const float* k_prime = (const float*)d_in[6];
    const float* v_prime = (const float*)d_in[7];
    const float* qW      = (const float*)d_in[8];
    const float* qb      = (const float*)d_in[9];
    const float* v1W     = (const float*)d_in[10];
    const float* v1b     = (const float*)d_in[11];
    const float* v2W     = (const float*)d_in[12];
    const float* v2b     = (const float*)d_in[13];
    float* out = (float*)d_out;

    static int inited = 0;
    if (!inited) {
        cudaFuncSetAttribute(gemm_mma<0>, cudaFuncAttributeMaxDynamicSharedMemorySize, SMEM_BYTES);
        cudaFuncSetAttribute(gemm_mma<1>, cudaFuncAttributeMaxDynamicSharedMemorySize, SMEM_BYTES);
        cudaFuncSetAttribute(gemm_mma<2>, cudaFuncAttributeMaxDynamicSharedMemorySize, SMEM_BYTES);
        inited = 1;
    }

    cvt_qw_kernel<<<4096, 256>>>(qW);
    gate_kernel<<<128, 256>>>(v_prime, v1W, v1b, v2W, v2b);
    ln_kernel<<<ROWS, 256>>>(x, qn_w, qn_b, kvn_w, kvn_b, k_prime);

    // qr = (xqn @ qW^T + qb) * sigmoid(q') / 32
    gemm_mma<0><<<dim3(H / BN, ROWS / BM, 1), 128, SMEM_BYTES>>>(qb, q_prime, nullptr);
    // E = exp(qr @ kr^T) + tile partial sums
    gemm_mma<1><<<dim3(SEQ / BN, SEQ / BM, BATCH), 128, SMEM_BYTES>>>(nullptr, nullptr, nullptr);
    // Zinv[b] = 1 / sum(E_b)
    zreduce_kernel<<<BATCH, 256>>>();
    // out = (E @ vr) * Zinv + xqn
    gemm_mma<2><<<dim3(H / BN, SEQ / BM, BATCH), 128, SMEM_BYTES>>>(nullptr, nullptr, out);
}